// round 11
// baseline (speedup 1.0000x reference)
#include <cuda_runtime.h>

// ============================================================================
// GCN 2-layer: out = GCN(relu(GCN(x, W1, b1)), W2, b2)  with symmetric norm
// ROOT-CAUSE FIX (R9, resubmitted R10 after broker failure): edge_index is
// int32 on the wire (JAX x64 disabled demotes the requested int64). Reading
// it as long long produced garbage indices -> wild atomics -> the 717 /
// illegal-access faults of R4-R9. A device-side dtype probe handles both
// layouts; all index uses are bounds-guarded so a bad index can never fault
// (only fail rel_err loudly).
// Pipeline (graph-capturable, allocation-free):
//   0. detect       : probe edge_index dtype (int32 vs int64)
//   1. init         : deg=1 (self loop), cnt=0, cursor=0
//   2. deg_count    : deg[col] += ew, cnt[col]++
//   3. scan1/2/3    : rowptr = exclusive_scan(cnt); dis = rsqrt(deg)
//   4. fill         : CSR by target node: (src, norm) pairs
//   5. gemm<128>    : g_t1 = x @ W1       (smem X tile, W streamed via L1)
//   6. agg<128,RELU>: g_h  = relu(gather-agg(g_t1) + b1)
//   7. gemm<64>     : g_t2 = g_h @ W2
//   8. agg<64>      : out  = gather-agg(g_t2) + b2
// ============================================================================

#define N_CAP 50000
#define E_CAP 800000

__device__ int   g_is64;
__device__ float g_deg[N_CAP];
__device__ float g_dis[N_CAP];
__device__ int   g_cnt[N_CAP];
__device__ int   g_rowptr[N_CAP + 1];
__device__ int   g_cursor[N_CAP];
__device__ int   g_blocksum[64];
__device__ int   g_csr_src[E_CAP];
__device__ float g_csr_w[E_CAP];
__device__ __align__(16) float g_t1[(size_t)N_CAP * 128];
__device__ __align__(16) float g_h[(size_t)N_CAP * 128];
__device__ __align__(16) float g_t2[(size_t)N_CAP * 64];

// ---------------------------------------------------------------------------
// edge-index readers (dtype-agnostic via g_is64)
// ---------------------------------------------------------------------------
__device__ __forceinline__ int edge_at(const void* ei, size_t idx) {
    if (g_is64) return (int)((const long long*)ei)[idx];
    return ((const int*)ei)[idx];
}

// ---------------------------------------------------------------------------
// 0. dtype probe: int32 pairs read as int64 have random node ids in the high
//    word -> huge values; true int64 node ids are all < n. 16 probes => the
//    misclassification probability is (1/50000)^16 ~ 0.
// ---------------------------------------------------------------------------
__global__ void detect_kernel(const void* ei, int n) {
    if (threadIdx.x == 0 && blockIdx.x == 0) {
        const long long* p = (const long long*)ei;
        int ok = 1;
        for (int i = 0; i < 16; ++i) {
            long long v = p[i];
            if (v < 0 || v >= n) { ok = 0; break; }
        }
        g_is64 = ok;
    }
}

// ---------------------------------------------------------------------------
// 1. init
// ---------------------------------------------------------------------------
__global__ void init_kernel(int n) {
    int i = blockIdx.x * blockDim.x + threadIdx.x;
    if (i < n) {
        g_deg[i] = 1.0f;   // self-loop weight
        g_cnt[i] = 0;
        g_cursor[i] = 0;
    }
}

// ---------------------------------------------------------------------------
// 2. degree + count histogram (bounds-guarded)
// ---------------------------------------------------------------------------
__global__ void deg_count_kernel(const void* __restrict__ ei,
                                 const float* __restrict__ ew, int e, int n) {
    int i = blockIdx.x * blockDim.x + threadIdx.x;
    if (i < e) {
        int c = edge_at(ei, (size_t)e + i);
        if ((unsigned)c < (unsigned)n) {
            atomicAdd(&g_deg[c], ew[i]);
            atomicAdd(&g_cnt[c], 1);
        }
    }
}

// ---------------------------------------------------------------------------
// 3. scan (3-phase) + dis = rsqrt(deg)
// ---------------------------------------------------------------------------
__global__ void scan1_kernel(int n) {
    __shared__ int wsum[32];
    int i = blockIdx.x * 1024 + threadIdx.x;
    int lane = threadIdx.x & 31, wid = threadIdx.x >> 5;
    int v = (i < n) ? g_cnt[i] : 0;
    int s = v;
#pragma unroll
    for (int d = 1; d < 32; d <<= 1) {
        int t = __shfl_up_sync(0xffffffffu, s, d);
        if (lane >= d) s += t;
    }
    if (lane == 31) wsum[wid] = s;
    __syncthreads();
    if (wid == 0) {
        int ws = wsum[lane];
#pragma unroll
        for (int d = 1; d < 32; d <<= 1) {
            int t = __shfl_up_sync(0xffffffffu, ws, d);
            if (lane >= d) ws += t;
        }
        wsum[lane] = ws;
    }
    __syncthreads();
    int off = (wid > 0) ? wsum[wid - 1] : 0;
    if (i < n) {
        g_rowptr[i] = off + s - v;              // block-local exclusive scan
        g_dis[i] = rsqrtf(g_deg[i]);            // deg >= 1 always (self loop)
    }
    if (threadIdx.x == 1023) g_blocksum[blockIdx.x] = off + s;
}

__global__ void scan2_kernel(int nb) {
    if (threadIdx.x == 0 && blockIdx.x == 0) {
        int run = 0;
        for (int b = 0; b < nb; ++b) {
            int t = g_blocksum[b];
            g_blocksum[b] = run;
            run += t;
        }
    }
}

__global__ void scan3_kernel(int n, int e) {
    int i = blockIdx.x * blockDim.x + threadIdx.x;
    if (i < n) g_rowptr[i] += g_blocksum[i >> 10];
    if (i == 0) g_rowptr[n] = e;
}

// ---------------------------------------------------------------------------
// 4. CSR fill with per-edge precomputed norm (bounds-guarded)
// ---------------------------------------------------------------------------
__global__ void fill_kernel(const void* __restrict__ ei,
                            const float* __restrict__ ew, int e, int n) {
    int i = blockIdx.x * blockDim.x + threadIdx.x;
    if (i < e) {
        int r = edge_at(ei, i);
        int c = edge_at(ei, (size_t)e + i);
        if ((unsigned)r < (unsigned)n && (unsigned)c < (unsigned)n) {
            float w = g_dis[r] * ew[i] * g_dis[c];
            int pos = g_rowptr[c] + atomicAdd(&g_cursor[c], 1);
            if ((unsigned)pos < (unsigned)e) {
                g_csr_src[pos] = r;
                g_csr_w[pos] = w;
            }
        }
    }
}

// ---------------------------------------------------------------------------
// 5/7. GEMM: OUT[n][FOUT] = X[n][128] @ W[128][FOUT]
//   FOUT=128: X = external x arg, OUT = g_t1
//   FOUT=64 : X = g_h,            OUT = g_t2
//   X tile (64 rows x 128) in static smem; W rows streamed (L1-resident,
//   same float4 address across a row-group -> broadcast hits).
// ---------------------------------------------------------------------------
template <int FOUT>
__global__ __launch_bounds__(256) void gemm_kernel(const float* __restrict__ Xext,
                                                   const float* __restrict__ W, int n) {
    const float* X;
    float* out;
    if constexpr (FOUT == 128) { X = Xext; out = g_t1; }
    else                       { X = g_h;  out = g_t2; }

    __shared__ float Xs[64][132];     // 33792 B static, +4 pad vs bank conflicts

    const int tid = threadIdx.x;
    const int m0 = blockIdx.x * 64;

    // Load X tile: 64 rows x 128 floats = 2048 float4 loads over 256 threads.
    for (int idx = tid; idx < 64 * 32; idx += 256) {
        int r = idx >> 5, q = idx & 31;
        float4 v = make_float4(0.f, 0.f, 0.f, 0.f);
        int row = m0 + r;
        if (row < n) v = *(const float4*)(X + (size_t)row * 128 + 4 * q);
        Xs[r][4 * q + 0] = v.x;
        Xs[r][4 * q + 1] = v.y;
        Xs[r][4 * q + 2] = v.z;
        Xs[r][4 * q + 3] = v.w;
    }
    __syncthreads();

    constexpr int CG  = FOUT / 4;      // col groups: 32 (F=128) or 16 (F=64)
    constexpr int RG  = 256 / CG;      // row groups: 8 or 16
    constexpr int RPT = 64 / RG;       // rows per thread: 8 or 4

    const int tx = tid % CG;           // this thread's 4-col group
    const int ty = tid / CG;           // this thread's base row

    float acc[RPT][4];
#pragma unroll
    for (int r = 0; r < RPT; ++r)
#pragma unroll
        for (int j = 0; j < 4; ++j) acc[r][j] = 0.f;

#pragma unroll 4
    for (int k = 0; k < 128; ++k) {
        float4 w = *(const float4*)(W + (size_t)k * FOUT + 4 * tx);
        float xv[RPT];
#pragma unroll
        for (int r = 0; r < RPT; ++r) xv[r] = Xs[ty + r * RG][k];
#pragma unroll
        for (int r = 0; r < RPT; ++r) {
            acc[r][0] += xv[r] * w.x;
            acc[r][1] += xv[r] * w.y;
            acc[r][2] += xv[r] * w.z;
            acc[r][3] += xv[r] * w.w;
        }
    }

#pragma unroll
    for (int r = 0; r < RPT; ++r) {
        int row = m0 + ty + r * RG;
        if (row < n) {
            float4 v = make_float4(acc[r][0], acc[r][1], acc[r][2], acc[r][3]);
            *(float4*)(out + (size_t)row * FOUT + 4 * tx) = v;
        }
    }
}

// ---------------------------------------------------------------------------
// 6/8. Aggregation: warp-per-node CSR gather (no scatter atomics).
//   F=128: t = g_t1, out = g_h  (+relu)
//   F=64 : t = g_t2, out = external d_out
//   acc = dis[n]^2 * t[n] + sum_e norm_e * t[src_e]; +bias
// ---------------------------------------------------------------------------
template <int F, bool RELU>
__global__ __launch_bounds__(256) void agg_kernel(const float* __restrict__ bias,
                                                  float* __restrict__ outext, int n) {
    const float* t;
    float* out;
    if constexpr (F == 128) { t = g_t1; out = g_h; }
    else                    { t = g_t2; out = outext; }

    int node = (blockIdx.x * blockDim.x + threadIdx.x) >> 5;
    int lane = threadIdx.x & 31;
    if (node >= n) return;

    constexpr int V = F / 32;           // 4 (F=128) or 2 (F=64)
    float acc[V];
    float dn = g_dis[node];
    float ws = dn * dn;                  // self-loop norm (weight 1)

    const float* selfp = t + (size_t)node * F + V * lane;
    if constexpr (V == 4) {
        float4 v = *(const float4*)selfp;
        acc[0] = ws * v.x; acc[1] = ws * v.y; acc[2] = ws * v.z; acc[3] = ws * v.w;
    } else {
        float2 v = *(const float2*)selfp;
        acc[0] = ws * v.x; acc[1] = ws * v.y;
    }

    int beg = g_rowptr[node], end = g_rowptr[node + 1];
    for (int base = beg; base < end; base += 32) {
        int cnt = min(32, end - base);
        int src = 0; float w = 0.f;
        if (lane < cnt) { src = g_csr_src[base + lane]; w = g_csr_w[base + lane]; }
#pragma unroll 4
        for (int j = 0; j < cnt; ++j) {
            int s = __shfl_sync(0xffffffffu, src, j);
            float wj = __shfl_sync(0xffffffffu, w, j);
            const float* p = t + (size_t)s * F + V * lane;
            if constexpr (V == 4) {
                float4 v = *(const float4*)p;
                acc[0] += wj * v.x; acc[1] += wj * v.y;
                acc[2] += wj * v.z; acc[3] += wj * v.w;
            } else {
                float2 v = *(const float2*)p;
                acc[0] += wj * v.x; acc[1] += wj * v.y;
            }
        }
    }

#pragma unroll
    for (int q = 0; q < V; ++q) {
        float r = acc[q] + bias[V * lane + q];
        if (RELU) r = fmaxf(r, 0.f);
        acc[q] = r;
    }
    float* o = out + (size_t)node * F + V * lane;
    if constexpr (V == 4) *(float4*)o = make_float4(acc[0], acc[1], acc[2], acc[3]);
    else                  *(float2*)o = make_float2(acc[0], acc[1]);
}

// ---------------------------------------------------------------------------
// launch
// ---------------------------------------------------------------------------
extern "C" void kernel_launch(void* const* d_in, const int* in_sizes, int n_in,
                              void* d_out, int out_size) {
    const float* x  = (const float*)d_in[0];
    const void*  ei = d_in[1];                  // int32 or int64 — probed on device
    const float* ew = (const float*)d_in[2];
    const float* W1 = (const float*)d_in[3];
    const float* b1 = (const float*)d_in[4];
    const float* W2 = (const float*)d_in[5];
    const float* b2 = (const float*)d_in[6];
    float* out = (float*)d_out;

    int n = in_sizes[0] / 128;   // 50000
    int e = in_sizes[2];         // 800000

    int nb_scan = (n + 1023) / 1024;

    detect_kernel<<<1, 32>>>(ei, n);
    init_kernel<<<(n + 255) / 256, 256>>>(n);
    deg_count_kernel<<<(e + 255) / 256, 256>>>(ei, ew, e, n);
    scan1_kernel<<<nb_scan, 1024>>>(n);
    scan2_kernel<<<1, 32>>>(nb_scan);
    scan3_kernel<<<(n + 255) / 256, 256>>>(n, e);
    fill_kernel<<<(e + 255) / 256, 256>>>(ei, ew, e, n);

    // Layer 1: g_t1 = x @ W1 ; g_h = relu(agg(g_t1) + b1)
    gemm_kernel<128><<<(n + 63) / 64, 256>>>(x, W1, n);
    agg_kernel<128, true><<<(n * 32 + 255) / 256, 256>>>(b1, out, n);

    // Layer 2: g_t2 = g_h @ W2 ; out = agg(g_t2) + b2
    gemm_kernel<64><<<(n + 63) / 64, 256>>>(x, W2, n);
    agg_kernel<64, false><<<(n * 32 + 255) / 256, 256>>>(b2, out, n);
}

// round 12
// speedup vs baseline: 1.1447x; 1.1447x over previous
#include <cuda_runtime.h>

// ============================================================================
// GCN 2-layer: out = GCN(relu(GCN(x, W1, b1)), W2, b2)  with symmetric norm
// R11: baseline PASSED (225.3us, rel_err 1.6e-7). This round swaps the plain
// FFMA GEMM for the f32x2 packed-FMA GEMM (halved fma-pipe issue count),
// now that the R4-R9 faults are proven to be the int32/int64 edge_index bug
// (fixed by the device-side dtype probe below), not the f32x2/dyn-smem path.
// Pipeline (graph-capturable, allocation-free):
//   0. detect       : probe edge_index dtype (int32 vs int64)
//   1. init         : deg=1 (self loop), cnt=0, cursor=0
//   2. deg_count    : deg[col] += ew, cnt[col]++
//   3. scan1/2/3    : rowptr = exclusive_scan(cnt); dis = rsqrt(deg)
//   4. fill         : CSR by target node: (src, norm) pairs
//   5. gemm<128>    : g_t1 = x @ W1      (f32x2 packed FMA, dyn smem)
//   6. agg<128,RELU>: g_h  = relu(gather-agg(g_t1) + b1)
//   7. gemm<64>     : g_t2 = g_h @ W2
//   8. agg<64>      : out  = gather-agg(g_t2) + b2
// ============================================================================

#define N_CAP 50000
#define E_CAP 800000

__device__ int   g_is64;
__device__ float g_deg[N_CAP];
__device__ float g_dis[N_CAP];
__device__ int   g_cnt[N_CAP];
__device__ int   g_rowptr[N_CAP + 1];
__device__ int   g_cursor[N_CAP];
__device__ int   g_blocksum[64];
__device__ int   g_csr_src[E_CAP];
__device__ float g_csr_w[E_CAP];
__device__ __align__(16) float g_t1[(size_t)N_CAP * 128];
__device__ __align__(16) float g_h[(size_t)N_CAP * 128];
__device__ __align__(16) float g_t2[(size_t)N_CAP * 64];

// ---------------------------------------------------------------------------
// helpers
// ---------------------------------------------------------------------------
__device__ __forceinline__ unsigned long long pack2(float lo, float hi) {
    unsigned long long r;
    asm("mov.b64 %0, {%1,%2};" : "=l"(r) : "f"(lo), "f"(hi));
    return r;
}
__device__ __forceinline__ void unpack2(unsigned long long v, float& lo, float& hi) {
    asm("mov.b64 {%0,%1}, %2;" : "=f"(lo), "=f"(hi) : "l"(v));
}
__device__ __forceinline__ void fma_f32x2(unsigned long long& d,
                                          unsigned long long a,
                                          unsigned long long b) {
    asm("fma.rn.f32x2 %0, %1, %2, %0;" : "+l"(d) : "l"(a), "l"(b));
}

__device__ __forceinline__ int edge_at(const void* ei, size_t idx) {
    if (g_is64) return (int)((const long long*)ei)[idx];
    return ((const int*)ei)[idx];
}

// ---------------------------------------------------------------------------
// 0. dtype probe: int32 pairs read as int64 have random node ids in the high
//    word -> huge values; true int64 node ids are all < n.
// ---------------------------------------------------------------------------
__global__ void detect_kernel(const void* ei, int n) {
    if (threadIdx.x == 0 && blockIdx.x == 0) {
        const long long* p = (const long long*)ei;
        int ok = 1;
        for (int i = 0; i < 16; ++i) {
            long long v = p[i];
            if (v < 0 || v >= n) { ok = 0; break; }
        }
        g_is64 = ok;
    }
}

// ---------------------------------------------------------------------------
// 1. init
// ---------------------------------------------------------------------------
__global__ void init_kernel(int n) {
    int i = blockIdx.x * blockDim.x + threadIdx.x;
    if (i < n) {
        g_deg[i] = 1.0f;   // self-loop weight
        g_cnt[i] = 0;
        g_cursor[i] = 0;
    }
}

// ---------------------------------------------------------------------------
// 2. degree + count histogram (bounds-guarded)
// ---------------------------------------------------------------------------
__global__ void deg_count_kernel(const void* __restrict__ ei,
                                 const float* __restrict__ ew, int e, int n) {
    int i = blockIdx.x * blockDim.x + threadIdx.x;
    if (i < e) {
        int c = edge_at(ei, (size_t)e + i);
        if ((unsigned)c < (unsigned)n) {
            atomicAdd(&g_deg[c], ew[i]);
            atomicAdd(&g_cnt[c], 1);
        }
    }
}

// ---------------------------------------------------------------------------
// 3. scan (3-phase) + dis = rsqrt(deg)
// ---------------------------------------------------------------------------
__global__ void scan1_kernel(int n) {
    __shared__ int wsum[32];
    int i = blockIdx.x * 1024 + threadIdx.x;
    int lane = threadIdx.x & 31, wid = threadIdx.x >> 5;
    int v = (i < n) ? g_cnt[i] : 0;
    int s = v;
#pragma unroll
    for (int d = 1; d < 32; d <<= 1) {
        int t = __shfl_up_sync(0xffffffffu, s, d);
        if (lane >= d) s += t;
    }
    if (lane == 31) wsum[wid] = s;
    __syncthreads();
    if (wid == 0) {
        int ws = wsum[lane];
#pragma unroll
        for (int d = 1; d < 32; d <<= 1) {
            int t = __shfl_up_sync(0xffffffffu, ws, d);
            if (lane >= d) ws += t;
        }
        wsum[lane] = ws;
    }
    __syncthreads();
    int off = (wid > 0) ? wsum[wid - 1] : 0;
    if (i < n) {
        g_rowptr[i] = off + s - v;              // block-local exclusive scan
        g_dis[i] = rsqrtf(g_deg[i]);            // deg >= 1 always (self loop)
    }
    if (threadIdx.x == 1023) g_blocksum[blockIdx.x] = off + s;
}

__global__ void scan2_kernel(int nb) {
    if (threadIdx.x == 0 && blockIdx.x == 0) {
        int run = 0;
        for (int b = 0; b < nb; ++b) {
            int t = g_blocksum[b];
            g_blocksum[b] = run;
            run += t;
        }
    }
}

__global__ void scan3_kernel(int n, int e) {
    int i = blockIdx.x * blockDim.x + threadIdx.x;
    if (i < n) g_rowptr[i] += g_blocksum[i >> 10];
    if (i == 0) g_rowptr[n] = e;
}

// ---------------------------------------------------------------------------
// 4. CSR fill with per-edge precomputed norm (bounds-guarded)
// ---------------------------------------------------------------------------
__global__ void fill_kernel(const void* __restrict__ ei,
                            const float* __restrict__ ew, int e, int n) {
    int i = blockIdx.x * blockDim.x + threadIdx.x;
    if (i < e) {
        int r = edge_at(ei, i);
        int c = edge_at(ei, (size_t)e + i);
        if ((unsigned)r < (unsigned)n && (unsigned)c < (unsigned)n) {
            float w = g_dis[r] * ew[i] * g_dis[c];
            int pos = g_rowptr[c] + atomicAdd(&g_cursor[c], 1);
            if ((unsigned)pos < (unsigned)e) {
                g_csr_src[pos] = r;
                g_csr_w[pos] = w;
            }
        }
    }
}

// ---------------------------------------------------------------------------
// 5/7. GEMM: OUT[n][FOUT] = X[n][128] @ W[128][FOUT], f32x2 packed over K
//   FOUT=128: X = external x arg, OUT = g_t1
//   FOUT=64 : X = g_h,            OUT = g_t2
//   - W pre-packed in smem as (W[2k][c], W[2k+1][c]) u64 pairs
//   - X tile in smem as K-pair u64s (row stride 66 u64 = conflict-free)
//   - thread owns 4 cols x RPT rows with 64-bit FMA2 accumulators
// ---------------------------------------------------------------------------
template <int FOUT>
__global__ __launch_bounds__(256) void gemm_kernel(const float* __restrict__ Xext,
                                                   const float* __restrict__ W, int n) {
    const float* X;
    float* out;
    if constexpr (FOUT == 128) { X = Xext; out = g_t1; }
    else                       { X = g_h;  out = g_t2; }

    extern __shared__ unsigned long long smem[];
    unsigned long long* Wsm = smem;                    // [64][FOUT] k-pairs
    unsigned long long* Xsm = smem + 64 * FOUT;        // [64][66]

    const int tid = threadIdx.x;
    const int m0 = blockIdx.x * 64;

    // Load + pack W (K-pairs along rows).
    for (int idx = tid; idx < 64 * FOUT; idx += 256) {
        int k2 = idx / FOUT, c = idx - k2 * FOUT;
        float lo = W[(size_t)(2 * k2) * FOUT + c];
        float hi = W[(size_t)(2 * k2 + 1) * FOUT + c];
        Wsm[idx] = pack2(lo, hi);
    }
    // Load X tile (64 rows x 128 f32 = 32 float4 per row).
    for (int idx = tid; idx < 64 * 32; idx += 256) {
        int r = idx >> 5, q = idx & 31;
        float4 v = make_float4(0.f, 0.f, 0.f, 0.f);
        int row = m0 + r;
        if (row < n) v = *(const float4*)(X + (size_t)row * 128 + 4 * q);
        *((float4*)(Xsm + (size_t)r * 66) + q) = v;
    }
    __syncthreads();

    constexpr int CG  = FOUT / 4;      // col groups: 32 (F=128) or 16 (F=64)
    constexpr int RG  = 256 / CG;      // row groups: 8 or 16
    constexpr int RPT = 64 / RG;       // rows per thread: 8 or 4

    const int tx = tid % CG;
    const int r0 = (tid / CG) * RPT;

    unsigned long long acc[RPT][4];
#pragma unroll
    for (int r = 0; r < RPT; ++r)
#pragma unroll
        for (int j = 0; j < 4; ++j) acc[r][j] = 0ull;

#pragma unroll 4
    for (int k2 = 0; k2 < 64; ++k2) {
        unsigned long long w[4];
#pragma unroll
        for (int j = 0; j < 4; ++j) w[j] = Wsm[k2 * FOUT + tx + CG * j];
#pragma unroll
        for (int r = 0; r < RPT; ++r) {
            unsigned long long xp = Xsm[(size_t)(r0 + r) * 66 + k2];
#pragma unroll
            for (int j = 0; j < 4; ++j) fma_f32x2(acc[r][j], xp, w[j]);
        }
    }

#pragma unroll
    for (int r = 0; r < RPT; ++r) {
        int row = m0 + r0 + r;
        if (row < n) {
#pragma unroll
            for (int j = 0; j < 4; ++j) {
                float lo, hi;
                unpack2(acc[r][j], lo, hi);
                out[(size_t)row * FOUT + tx + CG * j] = lo + hi;
            }
        }
    }
}

// ---------------------------------------------------------------------------
// 6/8. Aggregation: warp-per-node CSR gather (no scatter atomics).
//   F=128: t = g_t1, out = g_h  (+relu)
//   F=64 : t = g_t2, out = external d_out
//   acc = dis[n]^2 * t[n] + sum_e norm_e * t[src_e]; +bias
// ---------------------------------------------------------------------------
template <int F, bool RELU>
__global__ __launch_bounds__(256) void agg_kernel(const float* __restrict__ bias,
                                                  float* __restrict__ outext, int n) {
    const float* t;
    float* out;
    if constexpr (F == 128) { t = g_t1; out = g_h; }
    else                    { t = g_t2; out = outext; }

    int node = (blockIdx.x * blockDim.x + threadIdx.x) >> 5;
    int lane = threadIdx.x & 31;
    if (node >= n) return;

    constexpr int V = F / 32;           // 4 (F=128) or 2 (F=64)
    float acc[V];
    float dn = g_dis[node];
    float ws = dn * dn;                  // self-loop norm (weight 1)

    const float* selfp = t + (size_t)node * F + V * lane;
    if constexpr (V == 4) {
        float4 v = *(const float4*)selfp;
        acc[0] = ws * v.x; acc[1] = ws * v.y; acc[2] = ws * v.z; acc[3] = ws * v.w;
    } else {
        float2 v = *(const float2*)selfp;
        acc[0] = ws * v.x; acc[1] = ws * v.y;
    }

    int beg = g_rowptr[node], end = g_rowptr[node + 1];
    for (int base = beg; base < end; base += 32) {
        int cnt = min(32, end - base);
        int src = 0; float w = 0.f;
        if (lane < cnt) { src = g_csr_src[base + lane]; w = g_csr_w[base + lane]; }
#pragma unroll 4
        for (int j = 0; j < cnt; ++j) {
            int s = __shfl_sync(0xffffffffu, src, j);
            float wj = __shfl_sync(0xffffffffu, w, j);
            const float* p = t + (size_t)s * F + V * lane;
            if constexpr (V == 4) {
                float4 v = *(const float4*)p;
                acc[0] += wj * v.x; acc[1] += wj * v.y;
                acc[2] += wj * v.z; acc[3] += wj * v.w;
            } else {
                float2 v = *(const float2*)p;
                acc[0] += wj * v.x; acc[1] += wj * v.y;
            }
        }
    }

#pragma unroll
    for (int q = 0; q < V; ++q) {
        float r = acc[q] + bias[V * lane + q];
        if (RELU) r = fmaxf(r, 0.f);
        acc[q] = r;
    }
    float* o = out + (size_t)node * F + V * lane;
    if constexpr (V == 4) *(float4*)o = make_float4(acc[0], acc[1], acc[2], acc[3]);
    else                  *(float2*)o = make_float2(acc[0], acc[1]);
}

// ---------------------------------------------------------------------------
// launch
// ---------------------------------------------------------------------------
extern "C" void kernel_launch(void* const* d_in, const int* in_sizes, int n_in,
                              void* d_out, int out_size) {
    const float* x  = (const float*)d_in[0];
    const void*  ei = d_in[1];                  // int32 or int64 — probed on device
    const float* ew = (const float*)d_in[2];
    const float* W1 = (const float*)d_in[3];
    const float* b1 = (const float*)d_in[4];
    const float* W2 = (const float*)d_in[5];
    const float* b2 = (const float*)d_in[6];
    float* out = (float*)d_out;

    int n = in_sizes[0] / 128;   // 50000
    int e = in_sizes[2];         // 800000

    const int SMEM128 = (64 * 128 + 64 * 66) * 8;   // 99328 B
    const int SMEM64  = (64 * 64  + 64 * 66) * 8;   // 66560 B
    cudaFuncSetAttribute(gemm_kernel<128>, cudaFuncAttributeMaxDynamicSharedMemorySize, SMEM128);
    cudaFuncSetAttribute(gemm_kernel<64>,  cudaFuncAttributeMaxDynamicSharedMemorySize, SMEM64);

    int nb_scan = (n + 1023) / 1024;

    detect_kernel<<<1, 32>>>(ei, n);
    init_kernel<<<(n + 255) / 256, 256>>>(n);
    deg_count_kernel<<<(e + 255) / 256, 256>>>(ei, ew, e, n);
    scan1_kernel<<<nb_scan, 1024>>>(n);
    scan2_kernel<<<1, 32>>>(nb_scan);
    scan3_kernel<<<(n + 255) / 256, 256>>>(n, e);
    fill_kernel<<<(e + 255) / 256, 256>>>(ei, ew, e, n);

    // Layer 1: g_t1 = x @ W1 ; g_h = relu(agg(g_t1) + b1)
    gemm_kernel<128><<<(n + 63) / 64, 256, SMEM128>>>(x, W1, n);
    agg_kernel<128, true><<<(n * 32 + 255) / 256, 256>>>(b1, out, n);

    // Layer 2: g_t2 = g_h @ W2 ; out = agg(g_t2) + b2
    gemm_kernel<64><<<(n + 63) / 64, 256, SMEM64>>>(x, W2, n);
    agg_kernel<64, false><<<(n * 32 + 255) / 256, 256>>>(b2, out, n);
}